// round 15
// baseline (speedup 1.0000x reference)
#include <cuda_runtime.h>
#include <cstdint>

// ---------------- problem constants ----------------
#define BB       64
#define TT       2048
#define RNN_DIM  1024
#define EMB_DIM  512
#define ATT_DIM  128
#define N_FILT   32
#define KSIZE    31
#define PADW     15
#define TILE_T   128
#define NSPLIT   32          // t-splits for context kernel
#define TSEG     64          // TT / NSPLIT
#define NTAPS    62          // 2 channels x 31 taps
#define CATW     158         // TILE_T + KSIZE - 1

// init kernel block layout
#define PQ_BLOCKS   256      // 4 per batch; each covers 32 d
#define G_BLOCKS    16       // 4 taps each (64 slots >= 62 taps)
#define INIT_BLOCKS (PQ_BLOCKS + G_BLOCKS + 1)

// ---------------- scratch (no cudaMalloc allowed) ----------------
__device__ float g_pq[BB * ATT_DIM];
__device__ float g_G[NTAPS * ATT_DIM];       // fused conv x Wd matrix
__device__ float g_energies[BB * TT];

// ---------------- helpers ----------------
__device__ __forceinline__ float2 fma2(float2 a, float2 b, float2 c) {
    unsigned long long ra = *reinterpret_cast<unsigned long long*>(&a);
    unsigned long long rb = *reinterpret_cast<unsigned long long*>(&b);
    unsigned long long rc = *reinterpret_cast<unsigned long long*>(&c);
    unsigned long long rd;
    asm("fma.rn.f32x2 %0, %1, %2, %3;" : "=l"(rd) : "l"(ra), "l"(rb), "l"(rc));
    return *reinterpret_cast<float2*>(&rd);
}

__device__ __forceinline__ float tanh_hw(float x) {
    float y;
    asm("tanh.approx.f32 %0, %1;" : "=f"(y) : "f"(x));
    return y;
}

__device__ __forceinline__ float warp_max(float x) {
    #pragma unroll
    for (int o = 16; o; o >>= 1) x = fmaxf(x, __shfl_xor_sync(0xffffffffu, x, o));
    return x;
}
__device__ __forceinline__ float warp_sum(float x) {
    #pragma unroll
    for (int o = 16; o; o >>= 1) x += __shfl_xor_sync(0xffffffffu, x, o);
    return x;
}

// ---------------- K1: merged init (unchanged; DVFS-ramp bound) ----------------
__global__ __launch_bounds__(512) void init_kernel(
    const float* __restrict__ conv_w, const float* __restrict__ Wd,
    const float* __restrict__ hidden, const float* __restrict__ Wq,
    float* __restrict__ out)
{
    const int bid = blockIdx.x;
    const int tid = threadIdx.x;
    const int warp = tid >> 5, lane = tid & 31;

    if (bid < PQ_BLOCKS) {
        const int b = bid >> 2, q = bid & 3;
        __shared__ float4 h4[RNN_DIM / 4];            // 256 float4
        if (tid < 256)
            h4[tid] = reinterpret_cast<const float4*>(hidden + (size_t)b * RNN_DIM)[tid];
        __syncthreads();

        const int d0 = q * 32 + warp * 2;
        const float4* wqa = reinterpret_cast<const float4*>(Wq + (size_t)d0 * RNN_DIM);
        const float4* wqb = reinterpret_cast<const float4*>(Wq + (size_t)(d0 + 1) * RNN_DIM);

        float4 qa[8], qb[8];
        #pragma unroll
        for (int k = 0; k < 8; k++) { qa[k] = wqa[lane + 32 * k]; qb[k] = wqb[lane + 32 * k]; }

        float sa = 0.f, sb = 0.f;
        #pragma unroll
        for (int k = 0; k < 8; k++) {
            float4 h = h4[lane + 32 * k];
            sa += qa[k].x * h.x + qa[k].y * h.y + qa[k].z * h.z + qa[k].w * h.w;
            sb += qb[k].x * h.x + qb[k].y * h.y + qb[k].z * h.z + qb[k].w * h.w;
        }
        sa = warp_sum(sa);
        sb = warp_sum(sb);
        if (lane == 0) {
            g_pq[b * ATT_DIM + d0]     = sa;
            g_pq[b * ATT_DIM + d0 + 1] = sb;
        }
        return;
    }

    if (bid < PQ_BLOCKS + G_BLOCKS) {
        const int gb  = bid - PQ_BLOCKS;
        const int tap = gb * 4 + (tid >> 7);          // 0..63 (62,63 skipped)
        const int d   = tid & 127;
        if (tap < NTAPS) {
            const int c = tap / KSIZE, k = tap - c * KSIZE;
            float s = 0.f;
            #pragma unroll
            for (int f = 0; f < N_FILT; f++)
                s = fmaf(conv_w[(f * 2 + c) * KSIZE + k], Wd[d * N_FILT + f], s);
            g_G[tap * ATT_DIM + d] = s;
        }
        return;
    }

    // ---- zero out (BB*EMB_DIM = 32768 floats) ----
    float4* o4 = reinterpret_cast<float4*>(out);
    #pragma unroll
    for (int i = 0; i < 16; i++)
        o4[tid + 512 * i] = make_float4(0.f, 0.f, 0.f, 0.f);
}

// ---------------- K2: fused stencil-GEMM + tanh + energy (+mask) ----------------
// energies[b,t] = sum_d Wv[d] * tanh( pq[b,d] + pm[b,t,d] + sum_tap cat[c,t+k-15]*G[tap,d] )
// grid (T/TILE_T, B), 512 threads (16 warps). Warp w -> t = t0 + 8w .. +7.
// Lane owns d = 4*lane .. 4*lane+3.
// Key changes vs R14:
//  - cat stored as DUPLICATED float2 pairs (v,v): every FFMA2 b-operand is one
//    broadcast LDS.64; no float4 extraction, no MOV-pair building (-352 issues/warp)
//  - pm folded into accumulator init: pmr registers die before the main loop
__global__ __launch_bounds__(512, 1) void energies_kernel(
    const float* __restrict__ aw, const float* __restrict__ awc,
    const float* __restrict__ pm, const float* __restrict__ Wv,
    const unsigned char* __restrict__ mask)
{
    const int b  = blockIdx.y;
    const int t0 = blockIdx.x * TILE_T;
    const int tid = threadIdx.x;
    const int warp = tid >> 5, lane = tid & 31;
    const int wt0 = warp * 8;

    // prefetch pm for this warp's 8 t's (consumed at acc init right after sync)
    float4 pmr[8];
    {
        const float4* pm4 = reinterpret_cast<const float4*>(pm);
        const size_t base = ((size_t)b * TT + t0 + wt0) * 32 + lane;
        #pragma unroll
        for (int j = 0; j < 8; j++) pmr[j] = pm4[base + (size_t)j * 32];
    }

    __shared__ __align__(16) float  G_s[NTAPS * ATT_DIM];     // 31744 B
    __shared__ __align__(16) float2 catd_s[2][CATW];          // duplicated pairs, 2528 B
    __shared__ __align__(16) float  pq_s[ATT_DIM];
    __shared__ __align__(16) float  wv_s[ATT_DIM];

    for (int i = tid; i < NTAPS * ATT_DIM; i += 512) G_s[i] = g_G[i];
    for (int i = tid; i < 2 * CATW; i += 512) {
        int c = i / CATW, ii = i - c * CATW;
        int t = t0 - PADW + ii;
        float v = 0.f;
        if (t >= 0 && t < TT) v = (c == 0 ? aw : awc)[(size_t)b * TT + t];
        catd_s[c][ii] = make_float2(v, v);
    }
    if (tid < ATT_DIM) { pq_s[tid] = g_pq[b * ATT_DIM + tid]; wv_s[tid] = Wv[tid]; }
    __syncthreads();

    // acc init = pm (pq added in epilogue) — pmr dies here
    float2 accA[8], accB[8];
    #pragma unroll
    for (int j = 0; j < 8; j++) {
        accA[j] = make_float2(pmr[j].x, pmr[j].y);
        accB[j] = make_float2(pmr[j].z, pmr[j].w);
    }

    const float4* Gs4 = reinterpret_cast<const float4*>(G_s);

    #pragma unroll
    for (int c = 0; c < 2; c++) {
        const float2* cd = &catd_s[c][0];
        #pragma unroll
        for (int kb = 0; kb < 8; kb++) {
            const int k0 = kb * 4;
            const int NT = (kb == 7) ? 3 : 4;
            // 11 duplicated window pairs, each ONE broadcast LDS.64
            float2 w2[11];
            #pragma unroll
            for (int i = 0; i < 11; i++) w2[i] = cd[wt0 + k0 + i];

            #pragma unroll
            for (int dlt = 0; dlt < NT; dlt++) {
                const int tap = c * KSIZE + k0 + dlt;
                float4 g = Gs4[tap * 32 + lane];
                float2 gA = make_float2(g.x, g.y);
                float2 gB = make_float2(g.z, g.w);
                #pragma unroll
                for (int j = 0; j < 8; j++) {
                    accA[j] = fma2(gA, w2[dlt + j], accA[j]);
                    accB[j] = fma2(gB, w2[dlt + j], accB[j]);
                }
            }
        }
    }

    // epilogue: + pq, tanh, dot with Wv, warp-reduce over d, apply mask
    const float4 wv4 = reinterpret_cast<const float4*>(wv_s)[lane];
    const float4 pq4 = reinterpret_cast<const float4*>(pq_s)[lane];

    #pragma unroll
    for (int j = 0; j < 8; j++) {
        int t = t0 + wt0 + j;
        float x0 = tanh_hw(accA[j].x + pq4.x);
        float x1 = tanh_hw(accA[j].y + pq4.y);
        float x2 = tanh_hw(accB[j].x + pq4.z);
        float x3 = tanh_hw(accB[j].y + pq4.w);
        float p = x0 * wv4.x + x1 * wv4.y + x2 * wv4.z + x3 * wv4.w;
        p = warp_sum(p);
        if (lane == 0) {
            if (mask[(size_t)b * TT + t]) p = __int_as_float(0xff800000);  // -inf
            g_energies[(size_t)b * TT + t] = p;
        }
    }
}

// ---------------- K3: fused softmax + context partial + atomic reduce ----------------
// grid (NSPLIT, B), 128 threads. Direct GMEM streaming (at the LTS cap).
__global__ __launch_bounds__(128) void context_kernel(
    const float* __restrict__ memory, float* __restrict__ out)
{
    const int b = blockIdx.y, s = blockIdx.x;
    const int tid = threadIdx.x;
    const int warp = tid >> 5, lane = tid & 31;

    __shared__ float red[4];
    __shared__ float s_max, s_sum;
    __shared__ float ws[TSEG];

    // ---- softmax stats over all T of this batch (L2-resident, 8KB) ----
    const float4* e4 = reinterpret_cast<const float4*>(&g_energies[(size_t)b * TT]);
    float4 v[4];
    #pragma unroll
    for (int i = 0; i < 4; i++) v[i] = e4[tid + 128 * i];

    float m = v[0].x;
    #pragma unroll
    for (int i = 0; i < 4; i++)
        m = fmaxf(m, fmaxf(fmaxf(v[i].x, v[i].y), fmaxf(v[i].z, v[i].w)));
    m = warp_max(m);
    if (lane == 0) red[warp] = m;
    __syncthreads();
    if (tid == 0) s_max = fmaxf(fmaxf(red[0], red[1]), fmaxf(red[2], red[3]));
    __syncthreads();
    const float M = s_max;

    float sum = 0.f;
    #pragma unroll
    for (int i = 0; i < 4; i++)
        sum += __expf(v[i].x - M) + __expf(v[i].y - M)
             + __expf(v[i].z - M) + __expf(v[i].w - M);
    sum = warp_sum(sum);
    if (lane == 0) red[warp] = sum;
    __syncthreads();
    if (tid == 0) s_sum = red[0] + red[1] + red[2] + red[3];
    __syncthreads();
    const float inv = 1.0f / s_sum;

    // ---- weights for this segment ----
    const int t0 = s * TSEG;
    if (tid < TSEG)
        ws[tid] = __expf(g_energies[(size_t)b * TT + t0 + tid] - M) * inv;
    __syncthreads();

    // ---- weighted GEMV over the segment (direct GMEM, high MLP) ----
    const float4* m4 = reinterpret_cast<const float4*>(memory + ((size_t)b * TT + t0) * EMB_DIM);
    float4 acc = make_float4(0.f, 0.f, 0.f, 0.f);
    #pragma unroll 16
    for (int t = 0; t < TSEG; t++) {
        float w = ws[t];
        float4 mv = m4[(size_t)t * (EMB_DIM / 4) + tid];
        acc.x += w * mv.x; acc.y += w * mv.y; acc.z += w * mv.z; acc.w += w * mv.w;
    }

    float* o = out + (size_t)b * EMB_DIM + tid * 4;
    atomicAdd(o + 0, acc.x);
    atomicAdd(o + 1, acc.y);
    atomicAdd(o + 2, acc.z);
    atomicAdd(o + 3, acc.w);
}

// ---------------- launch ----------------
extern "C" void kernel_launch(void* const* d_in, const int* in_sizes, int n_in,
                              void* d_out, int out_size) {
    const float*         hidden = (const float*)d_in[0];          // (B, RNN_DIM)
    const float*         memory = (const float*)d_in[1];          // (B, T, EMB_DIM)
    const float*         pm     = (const float*)d_in[2];          // (B, T, ATT_DIM)
    const float*         aw     = (const float*)d_in[3];          // (B, T)
    const float*         awc    = (const float*)d_in[4];          // (B, T)
    const float*         Wq     = (const float*)d_in[5];          // (ATT_DIM, RNN_DIM)
    const float*         conv_w = (const float*)d_in[6];          // (N_FILT, 2, KSIZE)
    const float*         Wd     = (const float*)d_in[7];          // (ATT_DIM, N_FILT)
    const float*         Wv     = (const float*)d_in[8];          // (ATT_DIM,)
    const unsigned char* mask   = (const unsigned char*)d_in[9];  // (B, T) bool
    float* out = (float*)d_out;

    init_kernel<<<INIT_BLOCKS, 512>>>(conv_w, Wd, hidden, Wq, out);

    dim3 g2(TT / TILE_T, BB);
    energies_kernel<<<g2, 512>>>(aw, awc, pm, Wv, mask);

    dim3 g3(NSPLIT, BB);
    context_kernel<<<g3, 128>>>(memory, out);
}

// round 16
// speedup vs baseline: 1.1198x; 1.1198x over previous
#include <cuda_runtime.h>
#include <cstdint>

// ---------------- problem constants ----------------
#define BB       64
#define TT       2048
#define RNN_DIM  1024
#define EMB_DIM  512
#define ATT_DIM  128
#define N_FILT   32
#define KSIZE    31
#define PADW     15
#define TILE_T   64          // t-tile per energies block (256 thr, 2 blocks/SM)
#define NSPLIT   32          // t-splits for context kernel
#define TSEG     64          // TT / NSPLIT
#define NTAPS    62          // 2 channels x 31 taps
#define CATW     94          // TILE_T + KSIZE - 1

// init kernel block layout
#define PQ_BLOCKS   256      // 4 per batch; each covers 32 d
#define G_BLOCKS    16       // 4 taps each (64 slots >= 62 taps)
#define INIT_BLOCKS (PQ_BLOCKS + G_BLOCKS + 1)

// ---------------- scratch (no cudaMalloc allowed) ----------------
__device__ float g_pq[BB * ATT_DIM];
__device__ float g_G[NTAPS * ATT_DIM];       // fused conv x Wd matrix
__device__ float g_energies[BB * TT];

// ---------------- helpers ----------------
__device__ __forceinline__ float2 fma2(float2 a, float2 b, float2 c) {
    unsigned long long ra = *reinterpret_cast<unsigned long long*>(&a);
    unsigned long long rb = *reinterpret_cast<unsigned long long*>(&b);
    unsigned long long rc = *reinterpret_cast<unsigned long long*>(&c);
    unsigned long long rd;
    asm("fma.rn.f32x2 %0, %1, %2, %3;" : "=l"(rd) : "l"(ra), "l"(rb), "l"(rc));
    return *reinterpret_cast<float2*>(&rd);
}

__device__ __forceinline__ float tanh_hw(float x) {
    float y;
    asm("tanh.approx.f32 %0, %1;" : "=f"(y) : "f"(x));
    return y;
}

__device__ __forceinline__ float warp_max(float x) {
    #pragma unroll
    for (int o = 16; o; o >>= 1) x = fmaxf(x, __shfl_xor_sync(0xffffffffu, x, o));
    return x;
}
__device__ __forceinline__ float warp_sum(float x) {
    #pragma unroll
    for (int o = 16; o; o >>= 1) x += __shfl_xor_sync(0xffffffffu, x, o);
    return x;
}

// ---------------- K1: merged init (DVFS-ramp bound; leave alone) ----------------
__global__ __launch_bounds__(512) void init_kernel(
    const float* __restrict__ conv_w, const float* __restrict__ Wd,
    const float* __restrict__ hidden, const float* __restrict__ Wq,
    float* __restrict__ out)
{
    const int bid = blockIdx.x;
    const int tid = threadIdx.x;
    const int warp = tid >> 5, lane = tid & 31;

    if (bid < PQ_BLOCKS) {
        const int b = bid >> 2, q = bid & 3;
        __shared__ float4 h4[RNN_DIM / 4];            // 256 float4
        if (tid < 256)
            h4[tid] = reinterpret_cast<const float4*>(hidden + (size_t)b * RNN_DIM)[tid];
        __syncthreads();

        const int d0 = q * 32 + warp * 2;
        const float4* wqa = reinterpret_cast<const float4*>(Wq + (size_t)d0 * RNN_DIM);
        const float4* wqb = reinterpret_cast<const float4*>(Wq + (size_t)(d0 + 1) * RNN_DIM);

        float4 qa[8], qb[8];
        #pragma unroll
        for (int k = 0; k < 8; k++) { qa[k] = wqa[lane + 32 * k]; qb[k] = wqb[lane + 32 * k]; }

        float sa = 0.f, sb = 0.f;
        #pragma unroll
        for (int k = 0; k < 8; k++) {
            float4 h = h4[lane + 32 * k];
            sa += qa[k].x * h.x + qa[k].y * h.y + qa[k].z * h.z + qa[k].w * h.w;
            sb += qb[k].x * h.x + qb[k].y * h.y + qb[k].z * h.z + qb[k].w * h.w;
        }
        sa = warp_sum(sa);
        sb = warp_sum(sb);
        if (lane == 0) {
            g_pq[b * ATT_DIM + d0]     = sa;
            g_pq[b * ATT_DIM + d0 + 1] = sb;
        }
        return;
    }

    if (bid < PQ_BLOCKS + G_BLOCKS) {
        const int gb  = bid - PQ_BLOCKS;
        const int tap = gb * 4 + (tid >> 7);          // 0..63 (62,63 skipped)
        const int d   = tid & 127;
        if (tap < NTAPS) {
            const int c = tap / KSIZE, k = tap - c * KSIZE;
            float s = 0.f;
            #pragma unroll
            for (int f = 0; f < N_FILT; f++)
                s = fmaf(conv_w[(f * 2 + c) * KSIZE + k], Wd[d * N_FILT + f], s);
            g_G[tap * ATT_DIM + d] = s;
        }
        return;
    }

    // ---- zero out (BB*EMB_DIM = 32768 floats) ----
    float4* o4 = reinterpret_cast<float4*>(out);
    #pragma unroll
    for (int i = 0; i < 16; i++)
        o4[tid + 512 * i] = make_float4(0.f, 0.f, 0.f, 0.f);
}

// ---------------- K2: fused stencil-GEMM + tanh + energy (+mask) ----------------
// energies[b,t] = sum_d Wv[d] * tanh( pq[b,d] + pm[b,t,d] + sum_tap cat[c,t+k-15]*G[tap,d] )
// grid (T/TILE_T = 32, B), 256 threads (8 warps), 2 blocks/SM.
// Warp w -> t = t0 + 8w .. +7. Lane owns d = 4*lane .. 4*lane+3.
__global__ __launch_bounds__(256, 2) void energies_kernel(
    const float* __restrict__ aw, const float* __restrict__ awc,
    const float* __restrict__ pm, const float* __restrict__ Wv,
    const unsigned char* __restrict__ mask)
{
    const int b  = blockIdx.y;
    const int t0 = blockIdx.x * TILE_T;
    const int tid = threadIdx.x;
    const int warp = tid >> 5, lane = tid & 31;
    const int wt0 = warp * 8;

    // prefetch pm for this warp's 8 t's (consumed at acc init right after sync)
    float4 pmr[8];
    {
        const float4* pm4 = reinterpret_cast<const float4*>(pm);
        const size_t base = ((size_t)b * TT + t0 + wt0) * 32 + lane;
        #pragma unroll
        for (int j = 0; j < 8; j++) pmr[j] = pm4[base + (size_t)j * 32];
    }

    __shared__ __align__(16) float  G_s[NTAPS * ATT_DIM];     // 31744 B
    __shared__ __align__(16) float2 catd_s[2][CATW];          // duplicated pairs
    __shared__ __align__(16) float  pq_s[ATT_DIM];
    __shared__ __align__(16) float  wv_s[ATT_DIM];

    {   // G: 1984 float4 over 256 threads
        const float4* gg = reinterpret_cast<const float4*>(g_G);
        float4* gs = reinterpret_cast<float4*>(G_s);
        #pragma unroll
        for (int i = 0; i < 7; i++) gs[tid + 256 * i] = gg[tid + 256 * i];
        if (tid < 1984 - 7 * 256) gs[tid + 7 * 256] = gg[tid + 7 * 256];
    }
    for (int i = tid; i < 2 * CATW; i += 256) {
        int c = (i >= CATW), ii = i - c * CATW;
        int t = t0 - PADW + ii;
        float v = 0.f;
        if (t >= 0 && t < TT) v = (c == 0 ? aw : awc)[(size_t)b * TT + t];
        catd_s[c][ii] = make_float2(v, v);
    }
    if (tid < ATT_DIM) { pq_s[tid] = g_pq[b * ATT_DIM + tid]; wv_s[tid] = Wv[tid]; }
    __syncthreads();

    // acc init = pm (pq added in epilogue) — pmr dies here
    float2 accA[8], accB[8];
    #pragma unroll
    for (int j = 0; j < 8; j++) {
        accA[j] = make_float2(pmr[j].x, pmr[j].y);
        accB[j] = make_float2(pmr[j].z, pmr[j].w);
    }

    const float4* Gs4 = reinterpret_cast<const float4*>(G_s);

    #pragma unroll
    for (int c = 0; c < 2; c++) {
        const float2* cd = &catd_s[c][0];
        #pragma unroll
        for (int kb = 0; kb < 8; kb++) {
            const int k0 = kb * 4;
            const int NT = (kb == 7) ? 3 : 4;
            // 11 duplicated window pairs, each ONE broadcast LDS.64
            float2 w2[11];
            #pragma unroll
            for (int i = 0; i < 11; i++) w2[i] = cd[wt0 + k0 + i];

            #pragma unroll
            for (int dlt = 0; dlt < NT; dlt++) {
                const int tap = c * KSIZE + k0 + dlt;
                float4 g = Gs4[tap * 32 + lane];
                float2 gA = make_float2(g.x, g.y);
                float2 gB = make_float2(g.z, g.w);
                #pragma unroll
                for (int j = 0; j < 8; j++) {
                    accA[j] = fma2(gA, w2[dlt + j], accA[j]);
                    accB[j] = fma2(gB, w2[dlt + j], accB[j]);
                }
            }
        }
    }

    // epilogue: + pq, tanh, dot with Wv, warp-reduce over d, apply mask
    const float4 wv4 = reinterpret_cast<const float4*>(wv_s)[lane];
    const float4 pq4 = reinterpret_cast<const float4*>(pq_s)[lane];

    #pragma unroll
    for (int j = 0; j < 8; j++) {
        int t = t0 + wt0 + j;
        float x0 = tanh_hw(accA[j].x + pq4.x);
        float x1 = tanh_hw(accA[j].y + pq4.y);
        float x2 = tanh_hw(accB[j].x + pq4.z);
        float x3 = tanh_hw(accB[j].y + pq4.w);
        float p = x0 * wv4.x + x1 * wv4.y + x2 * wv4.z + x3 * wv4.w;
        p = warp_sum(p);
        if (lane == 0) {
            if (mask[(size_t)b * TT + t]) p = __int_as_float(0xff800000);  // -inf
            g_energies[(size_t)b * TT + t] = p;
        }
    }
}

// ---------------- K3: fused softmax + context partial + atomic reduce ----------------
// grid (NSPLIT, B), 128 threads. Direct GMEM streaming (at the LTS cap).
__global__ __launch_bounds__(128) void context_kernel(
    const float* __restrict__ memory, float* __restrict__ out)
{
    const int b = blockIdx.y, s = blockIdx.x;
    const int tid = threadIdx.x;
    const int warp = tid >> 5, lane = tid & 31;

    __shared__ float red[4];
    __shared__ float s_max, s_sum;
    __shared__ float ws[TSEG];

    // ---- softmax stats over all T of this batch (L2-resident, 8KB) ----
    const float4* e4 = reinterpret_cast<const float4*>(&g_energies[(size_t)b * TT]);
    float4 v[4];
    #pragma unroll
    for (int i = 0; i < 4; i++) v[i] = e4[tid + 128 * i];

    float m = v[0].x;
    #pragma unroll
    for (int i = 0; i < 4; i++)
        m = fmaxf(m, fmaxf(fmaxf(v[i].x, v[i].y), fmaxf(v[i].z, v[i].w)));
    m = warp_max(m);
    if (lane == 0) red[warp] = m;
    __syncthreads();
    if (tid == 0) s_max = fmaxf(fmaxf(red[0], red[1]), fmaxf(red[2], red[3]));
    __syncthreads();
    const float M = s_max;

    float sum = 0.f;
    #pragma unroll
    for (int i = 0; i < 4; i++)
        sum += __expf(v[i].x - M) + __expf(v[i].y - M)
             + __expf(v[i].z - M) + __expf(v[i].w - M);
    sum = warp_sum(sum);
    if (lane == 0) red[warp] = sum;
    __syncthreads();
    if (tid == 0) s_sum = red[0] + red[1] + red[2] + red[3];
    __syncthreads();
    const float inv = 1.0f / s_sum;

    // ---- weights for this segment ----
    const int t0 = s * TSEG;
    if (tid < TSEG)
        ws[tid] = __expf(g_energies[(size_t)b * TT + t0 + tid] - M) * inv;
    __syncthreads();

    // ---- weighted GEMV over the segment (direct GMEM, high MLP) ----
    const float4* m4 = reinterpret_cast<const float4*>(memory + ((size_t)b * TT + t0) * EMB_DIM);
    float4 acc = make_float4(0.f, 0.f, 0.f, 0.f);
    #pragma unroll 16
    for (int t = 0; t < TSEG; t++) {
        float w = ws[t];
        float4 mv = m4[(size_t)t * (EMB_DIM / 4) + tid];
        acc.x += w * mv.x; acc.y += w * mv.y; acc.z += w * mv.z; acc.w += w * mv.w;
    }

    float* o = out + (size_t)b * EMB_DIM + tid * 4;
    atomicAdd(o + 0, acc.x);
    atomicAdd(o + 1, acc.y);
    atomicAdd(o + 2, acc.z);
    atomicAdd(o + 3, acc.w);
}

// ---------------- launch ----------------
extern "C" void kernel_launch(void* const* d_in, const int* in_sizes, int n_in,
                              void* d_out, int out_size) {
    const float*         hidden = (const float*)d_in[0];          // (B, RNN_DIM)
    const float*         memory = (const float*)d_in[1];          // (B, T, EMB_DIM)
    const float*         pm     = (const float*)d_in[2];          // (B, T, ATT_DIM)
    const float*         aw     = (const float*)d_in[3];          // (B, T)
    const float*         awc    = (const float*)d_in[4];          // (B, T)
    const float*         Wq     = (const float*)d_in[5];          // (ATT_DIM, RNN_DIM)
    const float*         conv_w = (const float*)d_in[6];          // (N_FILT, 2, KSIZE)
    const float*         Wd     = (const float*)d_in[7];          // (ATT_DIM, N_FILT)
    const float*         Wv     = (const float*)d_in[8];          // (ATT_DIM,)
    const unsigned char* mask   = (const unsigned char*)d_in[9];  // (B, T) bool
    float* out = (float*)d_out;

    init_kernel<<<INIT_BLOCKS, 512>>>(conv_w, Wd, hidden, Wq, out);

    dim3 g2(TT / TILE_T, BB);
    energies_kernel<<<g2, 256>>>(aw, awc, pm, Wv, mask);

    dim3 g3(NSPLIT, BB);
    context_kernel<<<g3, 128>>>(memory, out);
}